// round 14
// baseline (speedup 1.0000x reference)
#include <cuda_runtime.h>
#include <cuda_bf16.h>
#include <cuda_fp16.h>
#include <math.h>
#include <cstdint>

#define SEQ_LEN 16384
#define D       1024
#define CSZ     128
#define NCH     128
#define NB      128

// ---------------- scratch (static device globals; no runtime allocs) --------
__device__ float g_K[(size_t)SEQ_LEN * D];
__device__ float g_V[(size_t)SEQ_LEN * D];
__device__ float g_Q[(size_t)SEQ_LEN * D];
__device__ float g_alpha[NCH];
__device__ __nv_bfloat16 g_xh[(size_t)SEQ_LEN * D];
__device__ __nv_bfloat16 g_xl[(size_t)SEQ_LEN * D];
__device__ __nv_bfloat16 g_Wh[3 * D * D];
__device__ __nv_bfloat16 g_Wl[3 * D * D];
__device__ __nv_bfloat16 g_Kh[(size_t)SEQ_LEN * D];
__device__ __nv_bfloat16 g_Kl[(size_t)SEQ_LEN * D];
__device__ __half        g_Qf[(size_t)SEQ_LEN * D];
__device__ __nv_bfloat16 g_Mh[D * D];
__device__ __nv_bfloat16 g_Ml[D * D];
__device__ __half        g_Mf[D * D];
__device__ __nv_bfloat16 g_errh[CSZ * D];
__device__ __nv_bfloat16 g_errl[CSZ * D];
__device__ __nv_bfloat16 g_e0h[CSZ * D];
__device__ __nv_bfloat16 g_e0l[CSZ * D];
__device__ unsigned g_cnt = 0;
__device__ volatile unsigned g_gen;

__device__ __forceinline__ float silu_f(float x) { return x / (1.0f + __expf(-x)); }

// ---------------- mma.sync helpers (baseline PTX, sm_80+) -------------------
__device__ __forceinline__ uint32_t smem_u32(const void* p) {
    uint32_t a;
    asm("{ .reg .u64 t; cvta.to.shared.u64 t, %1; cvt.u32.u64 %0, t; }" : "=r"(a) : "l"(p));
    return a;
}
__device__ __forceinline__ void ldm_x4(uint32_t* r, uint32_t addr) {
    asm volatile("ldmatrix.sync.aligned.m8n8.x4.shared.b16 {%0,%1,%2,%3}, [%4];"
                 : "=r"(r[0]), "=r"(r[1]), "=r"(r[2]), "=r"(r[3]) : "r"(addr));
}
__device__ __forceinline__ void ldm_x4_t(uint32_t* r, uint32_t addr) {
    asm volatile("ldmatrix.sync.aligned.m8n8.x4.trans.shared.b16 {%0,%1,%2,%3}, [%4];"
                 : "=r"(r[0]), "=r"(r[1]), "=r"(r[2]), "=r"(r[3]) : "r"(addr));
}
__device__ __forceinline__ void mma_bf16(float* c, const uint32_t* a, const uint32_t* b) {
    asm volatile("mma.sync.aligned.m16n8k16.row.col.f32.bf16.bf16.f32 "
                 "{%0,%1,%2,%3}, {%4,%5,%6,%7}, {%8,%9}, {%0,%1,%2,%3};"
                 : "+f"(c[0]), "+f"(c[1]), "+f"(c[2]), "+f"(c[3])
                 : "r"(a[0]), "r"(a[1]), "r"(a[2]), "r"(a[3]), "r"(b[0]), "r"(b[1]));
}
__device__ __forceinline__ void mma_f16(float* c, const uint32_t* a, const uint32_t* b) {
    asm volatile("mma.sync.aligned.m16n8k16.row.col.f32.f16.f16.f32 "
                 "{%0,%1,%2,%3}, {%4,%5,%6,%7}, {%8,%9}, {%0,%1,%2,%3};"
                 : "+f"(c[0]), "+f"(c[1]), "+f"(c[2]), "+f"(c[3])
                 : "r"(a[0]), "r"(a[1]), "r"(a[2]), "r"(a[3]), "r"(b[0]), "r"(b[1]));
}

// ---------------- grid barrier: atomic arrive, g_gen spin --------------------
__device__ __forceinline__ void grid_sync() {
    __syncthreads();
    if (threadIdx.x == 0) {
        unsigned gen = g_gen;
        __threadfence();
        unsigned a = atomicAdd(&g_cnt, 1u);
        if (a == NB - 1) {
            g_cnt = 0;
            __threadfence();
            g_gen = gen + 1;
        } else {
            while (g_gen == gen) { }
            __threadfence();
        }
    }
    __syncthreads();
}

// ---------------- fp32 -> bf16 hi/lo split -----------------------------------
__global__ __launch_bounds__(256) void convert_kernel(
    const float* __restrict__ src, __nv_bfloat16* __restrict__ hi, __nv_bfloat16* __restrict__ lo)
{
    int i = blockIdx.x * 256 + threadIdx.x;
    float4 v = ((const float4*)src)[i];
    __nv_bfloat16 h0 = __float2bfloat16(v.x);
    __nv_bfloat16 h1 = __float2bfloat16(v.y);
    __nv_bfloat16 h2 = __float2bfloat16(v.z);
    __nv_bfloat16 h3 = __float2bfloat16(v.w);
    ushort4 H, L;
    H.x = __bfloat16_as_ushort(h0); H.y = __bfloat16_as_ushort(h1);
    H.z = __bfloat16_as_ushort(h2); H.w = __bfloat16_as_ushort(h3);
    L.x = __bfloat16_as_ushort(__float2bfloat16(v.x - __bfloat162float(h0)));
    L.y = __bfloat16_as_ushort(__float2bfloat16(v.y - __bfloat162float(h1)));
    L.z = __bfloat16_as_ushort(__float2bfloat16(v.z - __bfloat162float(h2)));
    L.w = __bfloat16_as_ushort(__float2bfloat16(v.w - __bfloat162float(h3)));
    ((ushort4*)hi)[i] = H;
    ((ushort4*)lo)[i] = L;
}

// ---------------- HMMA projection GEMM: C = silu(A @ W^T), DOUBLE-buffered ---
#define ASTR 72
#define PSTG (4 * 128 * ASTR)
__global__ __launch_bounds__(256) void projmma_kernel(
    const __nv_bfloat16* __restrict__ xh, const __nv_bfloat16* __restrict__ xl,
    const __nv_bfloat16* __restrict__ Wh3, const __nv_bfloat16* __restrict__ Wl3,
    float* __restrict__ Ko, float* __restrict__ Vo, float* __restrict__ Qo)
{
    extern __shared__ __nv_bfloat16 smbf[];
    const int t = threadIdx.x;
    const int w = t >> 5, lane = t & 31;
    const int m0 = blockIdx.x * 128, n0 = blockIdx.y * 128;
    const int g = blockIdx.z;
    const __nv_bfloat16* Agh = xh + (size_t)m0 * D;
    const __nv_bfloat16* Agl = xl + (size_t)m0 * D;
    const __nv_bfloat16* Bgh = Wh3 + (size_t)g * D * D + (size_t)n0 * D;
    const __nv_bfloat16* Bgl = Wl3 + (size_t)g * D * D + (size_t)n0 * D;
    float* C = (g == 0) ? Ko : ((g == 1) ? Vo : Qo);

    const int wm = (w & 3) * 32, wn = (w >> 2) * 64;

    float acc[2][8][4];
    #pragma unroll
    for (int i = 0; i < 2; i++)
        #pragma unroll
        for (int j = 0; j < 8; j++)
            #pragma unroll
            for (int q = 0; q < 4; q++) acc[i][j][q] = 0.f;

    const int lt = lane >> 3, lr8 = lane & 7;
    const int a_row = (lt & 1) * 8 + lr8;
    const int a_k   = (lt >> 1) * 8;
    const int b_row = (lt >> 1) * 8 + lr8;
    const int b_k   = (lt & 1) * 8;

    auto load_stage = [&](int kc, int s) {
        __nv_bfloat16* st = smbf + s * PSTG;
        #pragma unroll
        for (int i = 0; i < 4; i++) {
            int idx = t + i * 256;
            int row = idx >> 3, c8 = (idx & 7) * 8;
            size_t go = (size_t)row * D + kc * 64 + c8;
            int so = row * ASTR + c8;
            *(uint4*)(st + so)                  = *(const uint4*)(Agh + go);
            *(uint4*)(st + 128 * ASTR + so)     = *(const uint4*)(Agl + go);
            *(uint4*)(st + 2 * 128 * ASTR + so) = *(const uint4*)(Bgh + go);
            *(uint4*)(st + 3 * 128 * ASTR + so) = *(const uint4*)(Bgl + go);
        }
    };

    load_stage(0, 0);
    __syncthreads();

    for (int kc = 0; kc < 16; kc++) {
        if (kc < 15) load_stage(kc + 1, (kc + 1) & 1);
        __nv_bfloat16* st = smbf + (kc & 1) * PSTG;
        const uint32_t uAh = smem_u32(st);
        const uint32_t uAl = smem_u32(st + 128 * ASTR);
        const uint32_t uBh = smem_u32(st + 2 * 128 * ASTR);
        const uint32_t uBl = smem_u32(st + 3 * 128 * ASTR);
        #pragma unroll
        for (int ks = 0; ks < 4; ks++) {
            uint32_t ah[2][4], al[2][4], bh[8][2], bl[8][2];
            #pragma unroll
            for (int mf = 0; mf < 2; mf++) {
                uint32_t off = (uint32_t)(((wm + mf * 16 + a_row) * ASTR + ks * 16 + a_k) * 2);
                ldm_x4(ah[mf], uAh + off);
                ldm_x4(al[mf], uAl + off);
            }
            #pragma unroll
            for (int j = 0; j < 4; j++) {
                uint32_t off = (uint32_t)(((wn + j * 16 + b_row) * ASTR + ks * 16 + b_k) * 2);
                uint32_t r[4];
                ldm_x4(r, uBh + off);
                bh[2 * j][0] = r[0]; bh[2 * j][1] = r[1];
                bh[2 * j + 1][0] = r[2]; bh[2 * j + 1][1] = r[3];
                ldm_x4(r, uBl + off);
                bl[2 * j][0] = r[0]; bl[2 * j][1] = r[1];
                bl[2 * j + 1][0] = r[2]; bl[2 * j + 1][1] = r[3];
            }
            #pragma unroll
            for (int mf = 0; mf < 2; mf++)
                #pragma unroll
                for (int nf = 0; nf < 8; nf++) {
                    mma_bf16(acc[mf][nf], ah[mf], bh[nf]);
                    mma_bf16(acc[mf][nf], ah[mf], bl[nf]);
                    mma_bf16(acc[mf][nf], al[mf], bh[nf]);
                }
        }
        __syncthreads();
    }
    const int gq = lane >> 2, t2 = (lane & 3) * 2;
    #pragma unroll
    for (int mf = 0; mf < 2; mf++) {
        const int row = m0 + wm + mf * 16 + gq;
        #pragma unroll
        for (int nf = 0; nf < 8; nf++) {
            const int col = n0 + wn + nf * 8 + t2;
            float2 v0, v1;
            v0.x = silu_f(acc[mf][nf][0]);
            v0.y = silu_f(acc[mf][nf][1]);
            v1.x = silu_f(acc[mf][nf][2]);
            v1.y = silu_f(acc[mf][nf][3]);
            *(float2*)(C + (size_t)row * D + col) = v0;
            *(float2*)(C + (size_t)(row + 8) * D + col) = v1;
        }
    }
}

// ---------------- l2norm; K -> bf16 split, Q -> fp16 -------------------------
__global__ __launch_bounds__(256) void l2norm_kernel(
    float* __restrict__ Kp, const float* __restrict__ Qp,
    __nv_bfloat16* __restrict__ Kh, __nv_bfloat16* __restrict__ Kl,
    __half* __restrict__ Qf)
{
    const bool isK = (blockIdx.y == 0);
    const float* P = isK ? Kp : Qp;
    size_t base = (size_t)blockIdx.x * D + threadIdx.x * 4;
    float4 v = *(const float4*)(P + base);
    float ss = v.x * v.x + v.y * v.y + v.z * v.z + v.w * v.w;
    #pragma unroll
    for (int o = 16; o > 0; o >>= 1) ss += __shfl_xor_sync(0xffffffffu, ss, o);
    __shared__ float ws[8];
    if ((threadIdx.x & 31) == 0) ws[threadIdx.x >> 5] = ss;
    __syncthreads();
    float tot = 0.f;
    #pragma unroll
    for (int i = 0; i < 8; i++) tot += ws[i];
    float sc = 1.0f / (sqrtf(tot) + 1e-8f);
    v.x *= sc; v.y *= sc; v.z *= sc; v.w *= sc;
    if (isK) {
        *(float4*)(Kp + base) = v;
        __nv_bfloat16 h0 = __float2bfloat16(v.x);
        __nv_bfloat16 h1 = __float2bfloat16(v.y);
        __nv_bfloat16 h2 = __float2bfloat16(v.z);
        __nv_bfloat16 h3 = __float2bfloat16(v.w);
        ushort4 HH, LL;
        HH.x = __bfloat16_as_ushort(h0); HH.y = __bfloat16_as_ushort(h1);
        HH.z = __bfloat16_as_ushort(h2); HH.w = __bfloat16_as_ushort(h3);
        LL.x = __bfloat16_as_ushort(__float2bfloat16(v.x - __bfloat162float(h0)));
        LL.y = __bfloat16_as_ushort(__float2bfloat16(v.y - __bfloat162float(h1)));
        LL.z = __bfloat16_as_ushort(__float2bfloat16(v.z - __bfloat162float(h2)));
        LL.w = __bfloat16_as_ushort(__float2bfloat16(v.w - __bfloat162float(h3)));
        *(ushort4*)(Kh + base) = HH;
        *(ushort4*)(Kl + base) = LL;
    } else {
        ushort4 F;
        F.x = __half_as_ushort(__float2half_rn(v.x));
        F.y = __half_as_ushort(__float2half_rn(v.y));
        F.z = __half_as_ushort(__float2half_rn(v.z));
        F.w = __half_as_ushort(__float2half_rn(v.w));
        *(ushort4*)(Qf + base) = F;
    }
}

// ---------------- per-chunk forgetting gate: alpha[c] ------------------------
__global__ __launch_bounds__(256) void alpha_kernel(
    const float* __restrict__ Kp, const float* __restrict__ Wf, float* __restrict__ alpha)
{
    const int c = blockIdx.x, t = threadIdx.x;
    float4 wf = *(const float4*)(Wf + t * 4);
    const float* Kc = Kp + (size_t)c * CSZ * D;
    float s = 0.f;
    #pragma unroll 4
    for (int r = 0; r < CSZ; r++) {
        float4 kv = *(const float4*)(Kc + (size_t)r * D + t * 4);
        s += kv.x * wf.x + kv.y * wf.y + kv.z * wf.z + kv.w * wf.w;
    }
    #pragma unroll
    for (int o = 16; o > 0; o >>= 1) s += __shfl_xor_sync(0xffffffffu, s, o);
    __shared__ float ws[8];
    if ((t & 31) == 0) ws[t >> 5] = s;
    __syncthreads();
    if (t == 0) {
        float tot = 0.f;
        #pragma unroll
        for (int i = 0; i < 8; i++) tot += ws[i];
        float mean = tot * (1.0f / CSZ);
        alpha[c] = 0.1f / (1.0f + __expf(-mean));
    }
}

// ---------------- persistent sequential kernel ------------------------------
// Phase 1 (update): unchanged 3-term bf16; S/M pinned in smem; publishes
// Mh/Ml (bf16) and Mf (fp16).
// Phase 2: uniform blocks — warps 0-3: err' tile 32x32 (3-term bf16);
// warps 4-7: out tile 32x32 (1-term fp16). mt = b>>5, n0 = (b&31)*32.
#define USTR_K 72
#define USTR_E 136
#define OA_STR 136
#define OB_STR 40
#define SMT_STR 132
#define PERS_OFF 53248
// phase-2 smem offsets (bf16 elems)
#define P2_KAH 0
#define P2_KAL 4352
#define P2_QA  8704
#define P2_BH  13056
#define P2_BL  18176
#define P2_BF  23296
__global__ __launch_bounds__(256, 1) void titan_seq(
    const __nv_bfloat16* __restrict__ Kh, const __nv_bfloat16* __restrict__ Kl,
    const __half* __restrict__ Qf,
    const __nv_bfloat16* __restrict__ e0h, const __nv_bfloat16* __restrict__ e0l,
    __nv_bfloat16* __restrict__ errh, __nv_bfloat16* __restrict__ errl,
    const float* __restrict__ Vp, const float* __restrict__ alpha,
    __nv_bfloat16* __restrict__ Mh, __nv_bfloat16* __restrict__ Ml,
    __half* __restrict__ Mf, float* __restrict__ out)
{
    extern __shared__ __nv_bfloat16 sm[];
    float* sS = (float*)(sm + PERS_OFF);
    float* sM = sS + 64 * SMT_STR;
    const int t = threadIdx.x, w = t >> 5, lane = t & 31;
    const int b = blockIdx.x;
    const int lt = lane >> 3, lr8 = lane & 7;
    const int gq = lane >> 2, t2 = (lane & 3) * 2;

    const int u_j0 = (b & 7) * 128, u_i0 = (b >> 3) * 64;
    const int o_mt = b >> 5, o_n0 = (b & 31) * 32;

    for (int i = t; i < 64 * SMT_STR; i += 256) {
        sS[i] = 0.f;
        sM[i] = 0.f;
    }

    for (int c = 0; c < NCH; c++) {
        // ================= update phase =====================================
        {
            __nv_bfloat16* sKh = sm;
            __nv_bfloat16* sKl = sm + 128 * USTR_K;
            __nv_bfloat16* sEh = sm + 2 * 128 * USTR_K;
            __nv_bfloat16* sEl = sm + 2 * 128 * USTR_K + 128 * USTR_E;
            const __nv_bfloat16* Kch = Kh + (size_t)c * CSZ * D;
            const __nv_bfloat16* Kcl = Kl + (size_t)c * CSZ * D;
            const __nv_bfloat16* Eh = (c == 0) ? e0h : errh;
            const __nv_bfloat16* El = (c == 0) ? e0l : errl;

            #pragma unroll
            for (int i = 0; i < 4; i++) {
                int idx = t + i * 256; int row = idx >> 3, q = idx & 7;
                *(uint4*)(sKh + row * USTR_K + q * 8) = *(const uint4*)(Kch + (size_t)row * D + u_i0 + q * 8);
                *(uint4*)(sKl + row * USTR_K + q * 8) = *(const uint4*)(Kcl + (size_t)row * D + u_i0 + q * 8);
            }
            #pragma unroll
            for (int i = 0; i < 8; i++) {
                int idx = t + i * 256; int row = idx >> 4, q = idx & 15;
                *(uint4*)(sEh + row * USTR_E + q * 8) = *(const uint4*)(Eh + (size_t)row * D + u_j0 + q * 8);
                *(uint4*)(sEl + row * USTR_E + q * 8) = *(const uint4*)(El + (size_t)row * D + u_j0 + q * 8);
            }
            __syncthreads();

            const int wi0 = (w & 3) * 16, wj0 = (w >> 2) * 64;
            const int a_r = (lt >> 1) * 8 + lr8, a_i = (lt & 1) * 8;
            const int b_k = (lt & 1) * 8 + lr8, b_n = (lt >> 1) * 8;
            const uint32_t uKh = smem_u32(sKh), uKl = smem_u32(sKl);
            const uint32_t uEh = smem_u32(sEh), uEl = smem_u32(sEl);

            float acc[8][4] = {};
            #pragma unroll
            for (int rs = 0; rs < 8; rs++) {
                uint32_t ah[4], al[4], bh[8][2], bl[8][2];
                uint32_t aoff = (uint32_t)(((rs * 16 + a_r) * USTR_K + wi0 + a_i) * 2);
                ldm_x4_t(ah, uKh + aoff);
                ldm_x4_t(al, uKl + aoff);
                #pragma unroll
                for (int jg = 0; jg < 4; jg++) {
                    uint32_t boff = (uint32_t)(((rs * 16 + b_k) * USTR_E + wj0 + jg * 16 + b_n) * 2);
                    uint32_t r[4];
                    ldm_x4_t(r, uEh + boff);
                    bh[2 * jg][0] = r[0]; bh[2 * jg][1] = r[1];
                    bh[2 * jg + 1][0] = r[2]; bh[2 * jg + 1][1] = r[3];
                    ldm_x4_t(r, uEl + boff);
                    bl[2 * jg][0] = r[0]; bl[2 * jg][1] = r[1];
                    bl[2 * jg + 1][0] = r[2]; bl[2 * jg + 1][1] = r[3];
                }
                #pragma unroll
                for (int nf = 0; nf < 8; nf++) {
                    mma_bf16(acc[nf], ah, bh[nf]);
                    mma_bf16(acc[nf], ah, bl[nf]);
                    mma_bf16(acc[nf], al, bh[nf]);
                }
            }
            const float alp = alpha[c];
            const float oma = 1.0f - alp;
            const float gs = ((c == 0) ? -1.0f : 1.0f) * (0.01f / CSZ);
            #pragma unroll
            for (int nf = 0; nf < 8; nf++) {
                #pragma unroll
                for (int h = 0; h < 2; h++) {
                    int rl = wi0 + gq + h * 8;
                    int cl = wj0 + nf * 8 + t2;
                    int sidx = rl * SMT_STR + cl;
                    float2 s = *(float2*)(sS + sidx);
                    float2 m = *(float2*)(sM + sidx);
                    s.x = 0.9f * s.x - gs * acc[nf][h * 2 + 0];
                    s.y = 0.9f * s.y - gs * acc[nf][h * 2 + 1];
                    m.x = oma * m.x + s.x;
                    m.y = oma * m.y + s.y;
                    *(float2*)(sS + sidx) = s;
                    *(float2*)(sM + sidx) = m;
                    __nv_bfloat162 mh, ml;
                    mh.x = __float2bfloat16(m.x); mh.y = __float2bfloat16(m.y);
                    ml.x = __float2bfloat16(m.x - __bfloat162float(mh.x));
                    ml.y = __float2bfloat16(m.y - __bfloat162float(mh.y));
                    size_t gidx = (size_t)(u_i0 + rl) * D + u_j0 + cl;
                    *(__nv_bfloat162*)(Mh + gidx) = mh;
                    *(__nv_bfloat162*)(Ml + gidx) = ml;
                    __half2 mf;
                    mf.x = __float2half_rn(m.x);
                    mf.y = __float2half_rn(m.y);
                    *(__half2*)(Mf + gidx) = mf;
                }
            }
        }
        grid_sync();

        // ================= combined out/err phase ===========================
        {
            const bool haveK = (c < NCH - 1);
            const __nv_bfloat16* KAh = Kh + ((size_t)(c + (haveK ? 1 : 0)) * CSZ + o_mt * 32) * D;
            const __nv_bfloat16* KAl = Kl + ((size_t)(c + (haveK ? 1 : 0)) * CSZ + o_mt * 32) * D;
            const __half* QA = Qf + ((size_t)c * CSZ + o_mt * 32) * D;
            const bool isKw = (w < 4);
            const int wl = isKw ? w : (w - 4);
            const int wm = (wl & 1) * 16, wn = ((wl >> 1) & 1) * 16;
            const int a_m = (lt & 1) * 8 + lr8, a_k = (lt >> 1) * 8;
            const int b_k = (lt & 1) * 8 + lr8, b_n = (lt >> 1) * 8;
            const uint32_t uKAh = smem_u32(sm + P2_KAH), uKAl = smem_u32(sm + P2_KAL);
            const uint32_t uQA  = smem_u32(sm + P2_QA);
            const uint32_t uBH  = smem_u32(sm + P2_BH),  uBL  = smem_u32(sm + P2_BL);
            const uint32_t uBF  = smem_u32(sm + P2_BF);

            float acc[2][4] = {};
            for (int kc = 0; kc < 8; kc++) {
                __syncthreads();
                #pragma unroll
                for (int i = 0; i < 2; i++) {                // A slabs: 32 x 128
                    int idx = t + i * 256; int row = idx >> 4, q = idx & 15;
                    if (haveK) {
                        *(uint4*)(sm + P2_KAH + row * OA_STR + q * 8) =
                            *(const uint4*)(KAh + (size_t)row * D + kc * 128 + q * 8);
                        *(uint4*)(sm + P2_KAL + row * OA_STR + q * 8) =
                            *(const uint4*)(KAl + (size_t)row * D + kc * 128 + q * 8);
                    }
                    *(uint4*)(sm + P2_QA + row * OA_STR + q * 8) =
                        *(const uint4*)((const __nv_bfloat16*)QA + (size_t)row * D + kc * 128 + q * 8);
                }
                #pragma unroll
                for (int i = 0; i < 2; i++) {                // B slabs: 128 x 32
                    int idx = t + i * 256; int row = idx >> 2, q = idx & 3;
                    if (haveK) {
                        *(uint4*)(sm + P2_BH + row * OB_STR + q * 8) =
                            *(const uint4*)(Mh + (size_t)(kc * 128 + row) * D + o_n0 + q * 8);
                        *(uint4*)(sm + P2_BL + row * OB_STR + q * 8) =
                            *(const uint4*)(Ml + (size_t)(kc * 128 + row) * D + o_n0 + q * 8);
                    }
                    *(uint4*)(sm + P2_BF + row * OB_STR + q * 8) =
                        *(const uint4*)((const __nv_bfloat16*)Mf + (size_t)(kc * 128 + row) * D + o_n0 + q * 8);
                }
                __syncthreads();
                if (isKw) {
                    if (haveK) {
                        #pragma unroll
                        for (int ks = 0; ks < 8; ks++) {
                            uint32_t ah[4], al[4], bh[2][2], bl[2][2];
                            uint32_t aoff = (uint32_t)(((wm + a_m) * OA_STR + ks * 16 + a_k) * 2);
                            ldm_x4(ah, uKAh + aoff);
                            ldm_x4(al, uKAl + aoff);
                            uint32_t boff = (uint32_t)(((ks * 16 + b_k) * OB_STR + wn + b_n) * 2);
                            uint32_t r[4];
                            ldm_x4_t(r, uBH + boff);
                            bh[0][0] = r[0]; bh[0][1] = r[1];
                            bh[1][0] = r[2]; bh[1][1] = r[3];
                            ldm_x4_t(r, uBL + boff);
                            bl[0][0] = r[0]; bl[0][1] = r[1];
                            bl[1][0] = r[2]; bl[1][1] = r[3];
                            #pragma unroll
                            for (int nf = 0; nf < 2; nf++) {
                                mma_bf16(acc[nf], ah, bh[nf]);
                                mma_bf16(acc[nf], ah, bl[nf]);
                                mma_bf16(acc[nf], al, bh[nf]);
                            }
                        }
                    }
                } else {
                    #pragma unroll
                    for (int ks = 0; ks < 8; ks++) {
                        uint32_t qa[4], bf[2][2];
                        uint32_t aoff = (uint32_t)(((wm + a_m) * OA_STR + ks * 16 + a_k) * 2);
                        ldm_x4(qa, uQA + aoff);
                        uint32_t boff = (uint32_t)(((ks * 16 + b_k) * OB_STR + wn + b_n) * 2);
                        uint32_t r[4];
                        ldm_x4_t(r, uBF + boff);
                        bf[0][0] = r[0]; bf[0][1] = r[1];
                        bf[1][0] = r[2]; bf[1][1] = r[3];
                        mma_f16(acc[0], qa, bf[0]);
                        mma_f16(acc[1], qa, bf[1]);
                    }
                }
            }
            if (isKw) {
                if (haveK) {
                    #pragma unroll
                    for (int nf = 0; nf < 2; nf++)
                        #pragma unroll
                        for (int h = 0; h < 2; h++) {
                            int rl = o_mt * 32 + wm + gq + h * 8;
                            int col = o_n0 + wn + nf * 8 + t2;
                            float2 vv = *(const float2*)(Vp + ((size_t)(c + 1) * CSZ + rl) * D + col);
                            float ex = acc[nf][h * 2] - vv.x;
                            float ey = acc[nf][h * 2 + 1] - vv.y;
                            __nv_bfloat162 hh, ll;
                            hh.x = __float2bfloat16(ex);
                            hh.y = __float2bfloat16(ey);
                            ll.x = __float2bfloat16(ex - __bfloat162float(hh.x));
                            ll.y = __float2bfloat16(ey - __bfloat162float(hh.y));
                            *(__nv_bfloat162*)(errh + (size_t)rl * D + col) = hh;
                            *(__nv_bfloat162*)(errl + (size_t)rl * D + col) = ll;
                        }
                }
            } else {
                #pragma unroll
                for (int nf = 0; nf < 2; nf++)
                    #pragma unroll
                    for (int h = 0; h < 2; h++) {
                        int row = c * CSZ + o_mt * 32 + wm + gq + h * 8;
                        int col = o_n0 + wn + nf * 8 + t2;
                        *(float2*)(out + (size_t)row * D + col) =
                            make_float2(acc[nf][h * 2], acc[nf][h * 2 + 1]);
                    }
            }
        }
        grid_sync();
    }
}

// ---------------- launcher ----------------------------------------------------
extern "C" void kernel_launch(void* const* d_in, const int* in_sizes, int n_in,
                              void* d_out, int out_size)
{
    const float* x  = (const float*)d_in[0];
    const float* Wk = (const float*)d_in[1];
    const float* Wv = (const float*)d_in[2];
    const float* Wq = (const float*)d_in[3];
    const float* Wf = (const float*)d_in[4];
    float* out = (float*)d_out;

    float *Kp, *Vp, *Qp, *alphap;
    __nv_bfloat16 *xh, *xl, *Wh, *Wl, *Khp, *Klp, *Mhp, *Mlp;
    __nv_bfloat16 *errhp, *errlp, *e0hp, *e0lp;
    __half *Qfp, *Mfp;
    cudaGetSymbolAddress((void**)&Kp, g_K);
    cudaGetSymbolAddress((void**)&Vp, g_V);
    cudaGetSymbolAddress((void**)&Qp, g_Q);
    cudaGetSymbolAddress((void**)&alphap, g_alpha);
    cudaGetSymbolAddress((void**)&xh, g_xh);
    cudaGetSymbolAddress((void**)&xl, g_xl);
    cudaGetSymbolAddress((void**)&Wh, g_Wh);
    cudaGetSymbolAddress((void**)&Wl, g_Wl);
    cudaGetSymbolAddress((void**)&Khp, g_Kh);
    cudaGetSymbolAddress((void**)&Klp, g_Kl);
    cudaGetSymbolAddress((void**)&Qfp, g_Qf);
    cudaGetSymbolAddress((void**)&Mhp, g_Mh);
    cudaGetSymbolAddress((void**)&Mlp, g_Ml);
    cudaGetSymbolAddress((void**)&Mfp, g_Mf);
    cudaGetSymbolAddress((void**)&errhp, g_errh);
    cudaGetSymbolAddress((void**)&errlp, g_errl);
    cudaGetSymbolAddress((void**)&e0hp, g_e0h);
    cudaGetSymbolAddress((void**)&e0lp, g_e0l);

    const int proj_smem = 2 * PSTG * 2;                              // 147456
    const int seq_smem  = PERS_OFF * 2 + 2 * 64 * SMT_STR * 4;       // 174080
    cudaFuncSetAttribute(projmma_kernel, cudaFuncAttributeMaxDynamicSharedMemorySize, proj_smem);
    cudaFuncSetAttribute(titan_seq, cudaFuncAttributeMaxDynamicSharedMemorySize, seq_smem);

    // Parallel phase.
    convert_kernel<<<SEQ_LEN * D / 1024, 256>>>(x, xh, xl);
    convert_kernel<<<D * D / 1024, 256>>>(Wk, Wh, Wl);
    convert_kernel<<<D * D / 1024, 256>>>(Wv, Wh + D * D, Wl + D * D);
    convert_kernel<<<D * D / 1024, 256>>>(Wq, Wh + 2 * D * D, Wl + 2 * D * D);
    projmma_kernel<<<dim3(SEQ_LEN / 128, D / 128, 3), 256, proj_smem>>>(
        xh, xl, Wh, Wl, Kp, Vp, Qp);
    l2norm_kernel<<<dim3(SEQ_LEN, 2), 256>>>(Kp, Qp, Khp, Klp, Qfp);
    alpha_kernel<<<NCH, 256>>>(Kp, Wf, alphap);
    convert_kernel<<<CSZ * D / 1024, 256>>>(Vp, e0hp, e0lp);   // err_0 = -V_0 via gs sign

    // Sequential phase.
    titan_seq<<<NB, 256, seq_smem>>>(Khp, Klp, Qfp, e0hp, e0lp,
                                     errhp, errlp, Vp, alphap,
                                     Mhp, Mlp, Mfp, out);
}

// round 15
// speedup vs baseline: 1.0817x; 1.0817x over previous
#include <cuda_runtime.h>
#include <cuda_bf16.h>
#include <math.h>
#include <cstdint>

#define SEQ_LEN 16384
#define D       1024
#define CSZ     128
#define NCH     128
#define NB      128

// ---------------- scratch (static device globals; no runtime allocs) --------
__device__ float g_K[(size_t)SEQ_LEN * D];
__device__ float g_V[(size_t)SEQ_LEN * D];
__device__ float g_Q[(size_t)SEQ_LEN * D];
__device__ float g_alpha[NCH];
__device__ __nv_bfloat16 g_xh[(size_t)SEQ_LEN * D];
__device__ __nv_bfloat16 g_xl[(size_t)SEQ_LEN * D];
__device__ __nv_bfloat16 g_Wh[3 * D * D];
__device__ __nv_bfloat16 g_Wl[3 * D * D];
__device__ __nv_bfloat16 g_Kh[(size_t)SEQ_LEN * D];
__device__ __nv_bfloat16 g_Kl[(size_t)SEQ_LEN * D];
__device__ __nv_bfloat16 g_Qh[(size_t)SEQ_LEN * D];
__device__ __nv_bfloat16 g_Ql[(size_t)SEQ_LEN * D];
__device__ __nv_bfloat16 g_Mh[D * D];
__device__ __nv_bfloat16 g_Ml[D * D];
__device__ __nv_bfloat16 g_errh[CSZ * D];
__device__ __nv_bfloat16 g_errl[CSZ * D];
__device__ __nv_bfloat16 g_e0h[CSZ * D];
__device__ __nv_bfloat16 g_e0l[CSZ * D];
__device__ unsigned g_cnt = 0;
__device__ volatile unsigned g_gen;

__device__ __forceinline__ float silu_f(float x) { return x / (1.0f + __expf(-x)); }

// ---------------- mma.sync helpers (baseline PTX, sm_80+) -------------------
__device__ __forceinline__ uint32_t smem_u32(const void* p) {
    uint32_t a;
    asm("{ .reg .u64 t; cvta.to.shared.u64 t, %1; cvt.u32.u64 %0, t; }" : "=r"(a) : "l"(p));
    return a;
}
__device__ __forceinline__ void ldm_x4(uint32_t* r, uint32_t addr) {
    asm volatile("ldmatrix.sync.aligned.m8n8.x4.shared.b16 {%0,%1,%2,%3}, [%4];"
                 : "=r"(r[0]), "=r"(r[1]), "=r"(r[2]), "=r"(r[3]) : "r"(addr));
}
__device__ __forceinline__ void ldm_x4_t(uint32_t* r, uint32_t addr) {
    asm volatile("ldmatrix.sync.aligned.m8n8.x4.trans.shared.b16 {%0,%1,%2,%3}, [%4];"
                 : "=r"(r[0]), "=r"(r[1]), "=r"(r[2]), "=r"(r[3]) : "r"(addr));
}
__device__ __forceinline__ void mma_bf16(float* c, const uint32_t* a, const uint32_t* b) {
    asm volatile("mma.sync.aligned.m16n8k16.row.col.f32.bf16.bf16.f32 "
                 "{%0,%1,%2,%3}, {%4,%5,%6,%7}, {%8,%9}, {%0,%1,%2,%3};"
                 : "+f"(c[0]), "+f"(c[1]), "+f"(c[2]), "+f"(c[3])
                 : "r"(a[0]), "r"(a[1]), "r"(a[2]), "r"(a[3]), "r"(b[0]), "r"(b[1]));
}

// ---------------- grid barrier: atomic arrive, g_gen spin --------------------
__device__ __forceinline__ void grid_sync() {
    __syncthreads();
    if (threadIdx.x == 0) {
        unsigned gen = g_gen;
        __threadfence();
        unsigned a = atomicAdd(&g_cnt, 1u);
        if (a == NB - 1) {
            g_cnt = 0;
            __threadfence();
            g_gen = gen + 1;
        } else {
            while (g_gen == gen) { }
            __threadfence();
        }
    }
    __syncthreads();
}

// ---------------- fp32 -> bf16 hi/lo split -----------------------------------
__global__ __launch_bounds__(256) void convert_kernel(
    const float* __restrict__ src, __nv_bfloat16* __restrict__ hi, __nv_bfloat16* __restrict__ lo)
{
    int i = blockIdx.x * 256 + threadIdx.x;
    float4 v = ((const float4*)src)[i];
    __nv_bfloat16 h0 = __float2bfloat16(v.x);
    __nv_bfloat16 h1 = __float2bfloat16(v.y);
    __nv_bfloat16 h2 = __float2bfloat16(v.z);
    __nv_bfloat16 h3 = __float2bfloat16(v.w);
    ushort4 H, L;
    H.x = __bfloat16_as_ushort(h0); H.y = __bfloat16_as_ushort(h1);
    H.z = __bfloat16_as_ushort(h2); H.w = __bfloat16_as_ushort(h3);
    L.x = __bfloat16_as_ushort(__float2bfloat16(v.x - __bfloat162float(h0)));
    L.y = __bfloat16_as_ushort(__float2bfloat16(v.y - __bfloat162float(h1)));
    L.z = __bfloat16_as_ushort(__float2bfloat16(v.z - __bfloat162float(h2)));
    L.w = __bfloat16_as_ushort(__float2bfloat16(v.w - __bfloat162float(h3)));
    ((ushort4*)hi)[i] = H;
    ((ushort4*)lo)[i] = L;
}

// ---------------- HMMA projection GEMM: C = silu(A @ W^T), DOUBLE-buffered ---
#define ASTR 72
#define PSTG (4 * 128 * ASTR)
__global__ __launch_bounds__(256) void projmma_kernel(
    const __nv_bfloat16* __restrict__ xh, const __nv_bfloat16* __restrict__ xl,
    const __nv_bfloat16* __restrict__ Wh3, const __nv_bfloat16* __restrict__ Wl3,
    float* __restrict__ Ko, float* __restrict__ Vo, float* __restrict__ Qo)
{
    extern __shared__ __nv_bfloat16 smbf[];
    const int t = threadIdx.x;
    const int w = t >> 5, lane = t & 31;
    const int m0 = blockIdx.x * 128, n0 = blockIdx.y * 128;
    const int g = blockIdx.z;
    const __nv_bfloat16* Agh = xh + (size_t)m0 * D;
    const __nv_bfloat16* Agl = xl + (size_t)m0 * D;
    const __nv_bfloat16* Bgh = Wh3 + (size_t)g * D * D + (size_t)n0 * D;
    const __nv_bfloat16* Bgl = Wl3 + (size_t)g * D * D + (size_t)n0 * D;
    float* C = (g == 0) ? Ko : ((g == 1) ? Vo : Qo);

    const int wm = (w & 3) * 32, wn = (w >> 2) * 64;

    float acc[2][8][4];
    #pragma unroll
    for (int i = 0; i < 2; i++)
        #pragma unroll
        for (int j = 0; j < 8; j++)
            #pragma unroll
            for (int q = 0; q < 4; q++) acc[i][j][q] = 0.f;

    const int lt = lane >> 3, lr8 = lane & 7;
    const int a_row = (lt & 1) * 8 + lr8;
    const int a_k   = (lt >> 1) * 8;
    const int b_row = (lt >> 1) * 8 + lr8;
    const int b_k   = (lt & 1) * 8;

    auto load_stage = [&](int kc, int s) {
        __nv_bfloat16* st = smbf + s * PSTG;
        #pragma unroll
        for (int i = 0; i < 4; i++) {
            int idx = t + i * 256;
            int row = idx >> 3, c8 = (idx & 7) * 8;
            size_t go = (size_t)row * D + kc * 64 + c8;
            int so = row * ASTR + c8;
            *(uint4*)(st + so)                  = *(const uint4*)(Agh + go);
            *(uint4*)(st + 128 * ASTR + so)     = *(const uint4*)(Agl + go);
            *(uint4*)(st + 2 * 128 * ASTR + so) = *(const uint4*)(Bgh + go);
            *(uint4*)(st + 3 * 128 * ASTR + so) = *(const uint4*)(Bgl + go);
        }
    };

    load_stage(0, 0);
    __syncthreads();

    for (int kc = 0; kc < 16; kc++) {
        if (kc < 15) load_stage(kc + 1, (kc + 1) & 1);
        __nv_bfloat16* st = smbf + (kc & 1) * PSTG;
        const uint32_t uAh = smem_u32(st);
        const uint32_t uAl = smem_u32(st + 128 * ASTR);
        const uint32_t uBh = smem_u32(st + 2 * 128 * ASTR);
        const uint32_t uBl = smem_u32(st + 3 * 128 * ASTR);
        #pragma unroll
        for (int ks = 0; ks < 4; ks++) {
            uint32_t ah[2][4], al[2][4], bh[8][2], bl[8][2];
            #pragma unroll
            for (int mf = 0; mf < 2; mf++) {
                uint32_t off = (uint32_t)(((wm + mf * 16 + a_row) * ASTR + ks * 16 + a_k) * 2);
                ldm_x4(ah[mf], uAh + off);
                ldm_x4(al[mf], uAl + off);
            }
            #pragma unroll
            for (int j = 0; j < 4; j++) {
                uint32_t off = (uint32_t)(((wn + j * 16 + b_row) * ASTR + ks * 16 + b_k) * 2);
                uint32_t r[4];
                ldm_x4(r, uBh + off);
                bh[2 * j][0] = r[0]; bh[2 * j][1] = r[1];
                bh[2 * j + 1][0] = r[2]; bh[2 * j + 1][1] = r[3];
                ldm_x4(r, uBl + off);
                bl[2 * j][0] = r[0]; bl[2 * j][1] = r[1];
                bl[2 * j + 1][0] = r[2]; bl[2 * j + 1][1] = r[3];
            }
            #pragma unroll
            for (int mf = 0; mf < 2; mf++)
                #pragma unroll
                for (int nf = 0; nf < 8; nf++) {
                    mma_bf16(acc[mf][nf], ah[mf], bh[nf]);
                    mma_bf16(acc[mf][nf], ah[mf], bl[nf]);
                    mma_bf16(acc[mf][nf], al[mf], bh[nf]);
                }
        }
        __syncthreads();
    }
    const int gq = lane >> 2, t2 = (lane & 3) * 2;
    #pragma unroll
    for (int mf = 0; mf < 2; mf++) {
        const int row = m0 + wm + mf * 16 + gq;
        #pragma unroll
        for (int nf = 0; nf < 8; nf++) {
            const int col = n0 + wn + nf * 8 + t2;
            float2 v0, v1;
            v0.x = silu_f(acc[mf][nf][0]);
            v0.y = silu_f(acc[mf][nf][1]);
            v1.x = silu_f(acc[mf][nf][2]);
            v1.y = silu_f(acc[mf][nf][3]);
            *(float2*)(C + (size_t)row * D + col) = v0;
            *(float2*)(C + (size_t)(row + 8) * D + col) = v1;
        }
    }
}

// ---------------- l2norm + bf16 split of K and Q -----------------------------
__global__ __launch_bounds__(256) void l2norm_kernel(
    float* __restrict__ Kp, const float* __restrict__ Qp,
    __nv_bfloat16* __restrict__ Kh, __nv_bfloat16* __restrict__ Kl,
    __nv_bfloat16* __restrict__ Qh, __nv_bfloat16* __restrict__ Ql)
{
    const bool isK = (blockIdx.y == 0);
    const float* P = isK ? Kp : Qp;
    size_t base = (size_t)blockIdx.x * D + threadIdx.x * 4;
    float4 v = *(const float4*)(P + base);
    float ss = v.x * v.x + v.y * v.y + v.z * v.z + v.w * v.w;
    #pragma unroll
    for (int o = 16; o > 0; o >>= 1) ss += __shfl_xor_sync(0xffffffffu, ss, o);
    __shared__ float ws[8];
    if ((threadIdx.x & 31) == 0) ws[threadIdx.x >> 5] = ss;
    __syncthreads();
    float tot = 0.f;
    #pragma unroll
    for (int i = 0; i < 8; i++) tot += ws[i];
    float sc = 1.0f / (sqrtf(tot) + 1e-8f);
    v.x *= sc; v.y *= sc; v.z *= sc; v.w *= sc;
    if (isK) *(float4*)(Kp + base) = v;
    __nv_bfloat16* H = isK ? Kh : Qh;
    __nv_bfloat16* L = isK ? Kl : Ql;
    __nv_bfloat16 h0 = __float2bfloat16(v.x);
    __nv_bfloat16 h1 = __float2bfloat16(v.y);
    __nv_bfloat16 h2 = __float2bfloat16(v.z);
    __nv_bfloat16 h3 = __float2bfloat16(v.w);
    ushort4 HH, LL;
    HH.x = __bfloat16_as_ushort(h0); HH.y = __bfloat16_as_ushort(h1);
    HH.z = __bfloat16_as_ushort(h2); HH.w = __bfloat16_as_ushort(h3);
    LL.x = __bfloat16_as_ushort(__float2bfloat16(v.x - __bfloat162float(h0)));
    LL.y = __bfloat16_as_ushort(__float2bfloat16(v.y - __bfloat162float(h1)));
    LL.z = __bfloat16_as_ushort(__float2bfloat16(v.z - __bfloat162float(h2)));
    LL.w = __bfloat16_as_ushort(__float2bfloat16(v.w - __bfloat162float(h3)));
    *(ushort4*)(H + base) = HH;
    *(ushort4*)(L + base) = LL;
}

// ---------------- per-chunk forgetting gate: alpha[c] ------------------------
__global__ __launch_bounds__(256) void alpha_kernel(
    const float* __restrict__ Kp, const float* __restrict__ Wf, float* __restrict__ alpha)
{
    const int c = blockIdx.x, t = threadIdx.x;
    float4 wf = *(const float4*)(Wf + t * 4);
    const float* Kc = Kp + (size_t)c * CSZ * D;
    float s = 0.f;
    #pragma unroll 4
    for (int r = 0; r < CSZ; r++) {
        float4 kv = *(const float4*)(Kc + (size_t)r * D + t * 4);
        s += kv.x * wf.x + kv.y * wf.y + kv.z * wf.z + kv.w * wf.w;
    }
    #pragma unroll
    for (int o = 16; o > 0; o >>= 1) s += __shfl_xor_sync(0xffffffffu, s, o);
    __shared__ float ws[8];
    if ((t & 31) == 0) ws[t >> 5] = s;
    __syncthreads();
    if (t == 0) {
        float tot = 0.f;
        #pragma unroll
        for (int i = 0; i < 8; i++) tot += ws[i];
        float mean = tot * (1.0f / CSZ);
        alpha[c] = 0.1f / (1.0f + __expf(-mean));
    }
}

// ---------------- persistent sequential kernel ------------------------------
// R13 structure + phase-2 double-buffering.
// Smem layout (bf16 elems):
//   [0, 54272)   phase staging union:
//     phase 1: sKh(128x72) sKl sEh(128x136) sEl  (53248 used)
//     phase 2: two 27136-elem stages {Ah(32x136) Al Bh(128x72) Bl}
//   [54272, +67584B*) persistent S then M tiles (64x132 fp32 each)
#define USTR_K 72
#define USTR_E 136
#define OA_STR 136
#define OB_STR 72
#define SMT_STR 132
#define O_STG  27136
#define PERS_OFF 54272
__global__ __launch_bounds__(256, 1) void titan_seq(
    const __nv_bfloat16* __restrict__ Kh, const __nv_bfloat16* __restrict__ Kl,
    const __nv_bfloat16* __restrict__ Qh, const __nv_bfloat16* __restrict__ Ql,
    const __nv_bfloat16* __restrict__ e0h, const __nv_bfloat16* __restrict__ e0l,
    __nv_bfloat16* __restrict__ errh, __nv_bfloat16* __restrict__ errl,
    const float* __restrict__ Vp, const float* __restrict__ alpha,
    __nv_bfloat16* __restrict__ Mh, __nv_bfloat16* __restrict__ Ml,
    float* __restrict__ out)
{
    extern __shared__ __nv_bfloat16 sm[];
    float* sS = (float*)(sm + PERS_OFF);
    float* sM = sS + 64 * SMT_STR;
    const int t = threadIdx.x, w = t >> 5, lane = t & 31;
    const int b = blockIdx.x;
    const int lt = lane >> 3, lr8 = lane & 7;
    const int gq = lane >> 2, t2 = (lane & 3) * 2;

    const int u_j0 = (b & 7) * 128, u_i0 = (b >> 3) * 64;

    for (int i = t; i < 64 * SMT_STR; i += 256) {
        sS[i] = 0.f;
        sM[i] = 0.f;
    }

    for (int c = 0; c < NCH; c++) {
        // ================= update phase: grad = Kc^T @ err; S,M; Mh/Ml ======
        {
            __nv_bfloat16* sKh = sm;
            __nv_bfloat16* sKl = sm + 128 * USTR_K;
            __nv_bfloat16* sEh = sm + 2 * 128 * USTR_K;
            __nv_bfloat16* sEl = sm + 2 * 128 * USTR_K + 128 * USTR_E;
            const __nv_bfloat16* Kch = Kh + (size_t)c * CSZ * D;
            const __nv_bfloat16* Kcl = Kl + (size_t)c * CSZ * D;
            const __nv_bfloat16* Eh = (c == 0) ? e0h : errh;
            const __nv_bfloat16* El = (c == 0) ? e0l : errl;

            #pragma unroll
            for (int i = 0; i < 4; i++) {
                int idx = t + i * 256; int row = idx >> 3, q = idx & 7;
                *(uint4*)(sKh + row * USTR_K + q * 8) = *(const uint4*)(Kch + (size_t)row * D + u_i0 + q * 8);
                *(uint4*)(sKl + row * USTR_K + q * 8) = *(const uint4*)(Kcl + (size_t)row * D + u_i0 + q * 8);
            }
            #pragma unroll
            for (int i = 0; i < 8; i++) {
                int idx = t + i * 256; int row = idx >> 4, q = idx & 15;
                *(uint4*)(sEh + row * USTR_E + q * 8) = *(const uint4*)(Eh + (size_t)row * D + u_j0 + q * 8);
                *(uint4*)(sEl + row * USTR_E + q * 8) = *(const uint4*)(El + (size_t)row * D + u_j0 + q * 8);
            }
            __syncthreads();

            const int wi0 = (w & 3) * 16, wj0 = (w >> 2) * 64;
            const int a_r = (lt >> 1) * 8 + lr8, a_i = (lt & 1) * 8;
            const int b_k = (lt & 1) * 8 + lr8, b_n = (lt >> 1) * 8;
            const uint32_t uKh = smem_u32(sKh), uKl = smem_u32(sKl);
            const uint32_t uEh = smem_u32(sEh), uEl = smem_u32(sEl);

            float acc[8][4] = {};
            #pragma unroll
            for (int rs = 0; rs < 8; rs++) {
                uint32_t ah[4], al[4], bh[8][2], bl[8][2];
                uint32_t aoff = (uint32_t)(((rs * 16 + a_r) * USTR_K + wi0 + a_i) * 2);
                ldm_x4_t(ah, uKh + aoff);
                ldm_x4_t(al, uKl + aoff);
                #pragma unroll
                for (int jg = 0; jg < 4; jg++) {
                    uint32_t boff = (uint32_t)(((rs * 16 + b_k) * USTR_E + wj0 + jg * 16 + b_n) * 2);
                    uint32_t r[4];
                    ldm_x4_t(r, uEh + boff);
                    bh[2 * jg][0] = r[0]; bh[2 * jg][1] = r[1];
                    bh[2 * jg + 1][0] = r[2]; bh[2 * jg + 1][1] = r[3];
                    ldm_x4_t(r, uEl + boff);
                    bl[2 * jg][0] = r[0]; bl[2 * jg][1] = r[1];
                    bl[2 * jg + 1][0] = r[2]; bl[2 * jg + 1][1] = r[3];
                }
                #pragma unroll
                for (int nf = 0; nf < 8; nf++) {
                    mma_bf16(acc[nf], ah, bh[nf]);
                    mma_bf16(acc[nf], ah, bl[nf]);
                    mma_bf16(acc[nf], al, bh[nf]);
                }
            }
            const float alp = alpha[c];
            const float oma = 1.0f - alp;
            const float gs = ((c == 0) ? -1.0f : 1.0f) * (0.01f / CSZ);
            #pragma unroll
            for (int nf = 0; nf < 8; nf++) {
                #pragma unroll
                for (int h = 0; h < 2; h++) {
                    int rl = wi0 + gq + h * 8;
                    int cl = wj0 + nf * 8 + t2;
                    int sidx = rl * SMT_STR + cl;
                    float2 s = *(float2*)(sS + sidx);
                    float2 m = *(float2*)(sM + sidx);
                    s.x = 0.9f * s.x - gs * acc[nf][h * 2 + 0];
                    s.y = 0.9f * s.y - gs * acc[nf][h * 2 + 1];
                    m.x = oma * m.x + s.x;
                    m.y = oma * m.y + s.y;
                    *(float2*)(sS + sidx) = s;
                    *(float2*)(sM + sidx) = m;
                    __nv_bfloat162 mh, ml;
                    mh.x = __float2bfloat16(m.x); mh.y = __float2bfloat16(m.y);
                    ml.x = __float2bfloat16(m.x - __bfloat162float(mh.x));
                    ml.y = __float2bfloat16(m.y - __bfloat162float(mh.y));
                    size_t gidx = (size_t)(u_i0 + rl) * D + u_j0 + cl;
                    *(__nv_bfloat162*)(Mh + gidx) = mh;
                    *(__nv_bfloat162*)(Ml + gidx) = ml;
                }
            }
        }
        grid_sync();

        // ================= outerr phase (double-buffered stages) ============
        {
            const int mt = b >> 4;
            const bool isQ = (mt < 4);
            if (c < NCH - 1 || isQ) {
                const int n0 = (b & 15) * 64;
                const __nv_bfloat16* Agh = isQ ? (Qh + ((size_t)c * CSZ + mt * 32) * D)
                                               : (Kh + ((size_t)(c + 1) * CSZ + (mt - 4) * 32) * D);
                const __nv_bfloat16* Agl = isQ ? (Ql + ((size_t)c * CSZ + mt * 32) * D)
                                               : (Kl + ((size_t)(c + 1) * CSZ + (mt - 4) * 32) * D);
                const int wm = (w & 1) * 16, wn = (w >> 1) * 16;
                const int a_m = (lt & 1) * 8 + lr8, a_k = (lt >> 1) * 8;
                const int b_k = (lt & 1) * 8 + lr8, b_n = (lt >> 1) * 8;

                auto load_stage = [&](int kc, int s) {
                    __nv_bfloat16* st = sm + s * O_STG;
                    #pragma unroll
                    for (int i = 0; i < 2; i++) {            // A: 32 x 128
                        int idx = t + i * 256; int row = idx >> 4, q = idx & 15;
                        *(uint4*)(st + row * OA_STR + q * 8) =
                            *(const uint4*)(Agh + (size_t)row * D + kc * 128 + q * 8);
                        *(uint4*)(st + 4352 + row * OA_STR + q * 8) =
                            *(const uint4*)(Agl + (size_t)row * D + kc * 128 + q * 8);
                    }
                    #pragma unroll
                    for (int i = 0; i < 4; i++) {            // B: 128 x 64
                        int idx = t + i * 256; int row = idx >> 3, q = idx & 7;
                        *(uint4*)(st + 8704 + row * OB_STR + q * 8) =
                            *(const uint4*)(Mh + (size_t)(kc * 128 + row) * D + n0 + q * 8);
                        *(uint4*)(st + 17920 + row * OB_STR + q * 8) =
                            *(const uint4*)(Ml + (size_t)(kc * 128 + row) * D + n0 + q * 8);
                    }
                };

                float acc[2][4] = {};
                load_stage(0, 0);
                __syncthreads();
                for (int kc = 0; kc < 8; kc++) {
                    if (kc < 7) load_stage(kc + 1, (kc + 1) & 1);
                    __nv_bfloat16* st = sm + (kc & 1) * O_STG;
                    const uint32_t uAh = smem_u32(st);
                    const uint32_t uAl = smem_u32(st + 4352);
                    const uint32_t uBh = smem_u32(st + 8704);
                    const uint32_t uBl = smem_u32(st + 17920);
                    #pragma unroll
                    for (int ks = 0; ks < 8; ks++) {
                        uint32_t ah[4], al[4], bh[2][2], bl[2][2];
                        uint32_t aoff = (uint32_t)(((wm + a_m) * OA_STR + ks * 16 + a_k) * 2);
                        ldm_x4(ah, uAh + aoff);
                        ldm_x4(al, uAl + aoff);
                        uint32_t boff = (uint32_t)(((ks * 16 + b_k) * OB_STR + wn + b_n) * 2);
                        uint32_t r[4];
                        ldm_x4_t(r, uBh + boff);
                        bh[0][0] = r[0]; bh[0][1] = r[1];
                        bh[1][0] = r[2]; bh[1][1] = r[3];
                        ldm_x4_t(r, uBl + boff);
                        bl[0][0] = r[0]; bl[0][1] = r[1];
                        bl[1][0] = r[2]; bl[1][1] = r[3];
                        #pragma unroll
                        for (int nf = 0; nf < 2; nf++) {
                            mma_bf16(acc[nf], ah, bh[nf]);
                            mma_bf16(acc[nf], ah, bl[nf]);
                            mma_bf16(acc[nf], al, bh[nf]);
                        }
                    }
                    __syncthreads();
                }
                if (isQ) {
                    #pragma unroll
                    for (int nf = 0; nf < 2; nf++)
                        #pragma unroll
                        for (int h = 0; h < 2; h++) {
                            int row = c * CSZ + mt * 32 + wm + gq + h * 8;
                            int col = n0 + wn + nf * 8 + t2;
                            *(float2*)(out + (size_t)row * D + col) =
                                make_float2(acc[nf][h * 2], acc[nf][h * 2 + 1]);
                        }
                } else {
                    #pragma unroll
                    for (int nf = 0; nf < 2; nf++)
                        #pragma unroll
                        for (int h = 0; h < 2; h++) {
                            int rl = (mt - 4) * 32 + wm + gq + h * 8;
                            int col = n0 + wn + nf * 8 + t2;
                            float2 vv = *(const float2*)(Vp + ((size_t)(c + 1) * CSZ + rl) * D + col);
                            float ex = acc[nf][h * 2] - vv.x;
                            float ey = acc[nf][h * 2 + 1] - vv.y;
                            __nv_bfloat162 hh, ll;
                            hh.x = __float2bfloat16(ex);
                            hh.y = __float2bfloat16(ey);
                            ll.x = __float2bfloat16(ex - __bfloat162float(hh.x));
                            ll.y = __float2bfloat16(ey - __bfloat162float(hh.y));
                            *(__nv_bfloat162*)(errh + (size_t)rl * D + col) = hh;
                            *(__nv_bfloat162*)(errl + (size_t)rl * D + col) = ll;
                        }
                }
            }
        }
        grid_sync();
    }
}

// ---------------- launcher ----------------------------------------------------
extern "C" void kernel_launch(void* const* d_in, const int* in_sizes, int n_in,
                              void* d_out, int out_size)
{
    const float* x  = (const float*)d_in[0];
    const float* Wk = (const float*)d_in[1];
    const float* Wv = (const float*)d_in[2];
    const float* Wq = (const float*)d_in[3];
    const float* Wf = (const float*)d_in[4];
    float* out = (float*)d_out;

    float *Kp, *Vp, *Qp, *alphap;
    __nv_bfloat16 *xh, *xl, *Wh, *Wl, *Khp, *Klp, *Qhp, *Qlp, *Mhp, *Mlp;
    __nv_bfloat16 *errhp, *errlp, *e0hp, *e0lp;
    cudaGetSymbolAddress((void**)&Kp, g_K);
    cudaGetSymbolAddress((void**)&Vp, g_V);
    cudaGetSymbolAddress((void**)&Qp, g_Q);
    cudaGetSymbolAddress((void**)&alphap, g_alpha);
    cudaGetSymbolAddress((void**)&xh, g_xh);
    cudaGetSymbolAddress((void**)&xl, g_xl);
    cudaGetSymbolAddress((void**)&Wh, g_Wh);
    cudaGetSymbolAddress((void**)&Wl, g_Wl);
    cudaGetSymbolAddress((void**)&Khp, g_Kh);
    cudaGetSymbolAddress((void**)&Klp, g_Kl);
    cudaGetSymbolAddress((void**)&Qhp, g_Qh);
    cudaGetSymbolAddress((void**)&Qlp, g_Ql);
    cudaGetSymbolAddress((void**)&Mhp, g_Mh);
    cudaGetSymbolAddress((void**)&Mlp, g_Ml);
    cudaGetSymbolAddress((void**)&errhp, g_errh);
    cudaGetSymbolAddress((void**)&errlp, g_errl);
    cudaGetSymbolAddress((void**)&e0hp, g_e0h);
    cudaGetSymbolAddress((void**)&e0lp, g_e0l);

    const int proj_smem = 2 * PSTG * 2;                              // 147456
    const int seq_smem  = PERS_OFF * 2 + 2 * 64 * SMT_STR * 4;       // 108544 + 67584 = 176128
    cudaFuncSetAttribute(projmma_kernel, cudaFuncAttributeMaxDynamicSharedMemorySize, proj_smem);
    cudaFuncSetAttribute(titan_seq, cudaFuncAttributeMaxDynamicSharedMemorySize, seq_smem);

    // Parallel phase.
    convert_kernel<<<SEQ_LEN * D / 1024, 256>>>(x, xh, xl);
    convert_kernel<<<D * D / 1024, 256>>>(Wk, Wh, Wl);
    convert_kernel<<<D * D / 1024, 256>>>(Wv, Wh + D * D, Wl + D * D);
    convert_kernel<<<D * D / 1024, 256>>>(Wq, Wh + 2 * D * D, Wl + 2 * D * D);
    projmma_kernel<<<dim3(SEQ_LEN / 128, D / 128, 3), 256, proj_smem>>>(
        xh, xl, Wh, Wl, Kp, Vp, Qp);
    l2norm_kernel<<<dim3(SEQ_LEN, 2), 256>>>(Kp, Qp, Khp, Klp, Qhp, Qlp);
    alpha_kernel<<<NCH, 256>>>(Kp, Wf, alphap);
    convert_kernel<<<CSZ * D / 1024, 256>>>(Vp, e0hp, e0lp);   // err_0 = -V_0 via gs sign

    // Sequential phase: persistent kernel; S/M pinned in smem; phase-2 DB.
    titan_seq<<<NB, 256, seq_smem>>>(Khp, Klp, Qhp, Qlp, e0hp, e0lp,
                                     errhp, errlp, Vp, alphap,
                                     Mhp, Mlp, out);
}